// round 1
// baseline (speedup 1.0000x reference)
#include <cuda_runtime.h>
#include <math.h>

// Problem dims
#define N 512     // rows of feat_x
#define M 512     // set size
#define D 512     // INPUT_DIM
#define HG 256    // HIDDEN_DIM (g)
#define R 256     // REP_DIM
#define H 128     // SCORE_HIDDEN

// ---------------- device scratch (no allocs allowed) ----------------
__device__ float d_rep[3][N][R];       // 0=x, 1=pos, 2=neg
__device__ float d_norm2[3][N];        // squared norms of rep rows
__device__ float d_Wxd[R * H];         // Wx - Wd
__device__ float d_Wyd[R * H];         // Wy + Wd
__device__ float d_A[N * H];           // x_rep @ Wxd + s_b1
__device__ float d_Bt[2][H * M];       // transposed: [k][m], per set
__device__ float d_G[2][N * M];        // Gram x_rep @ y_rep^T
__device__ float d_W[2][N * M];        // softmax weights
__device__ float d_Ud[N * R];          // U_pos - U_neg

__device__ __forceinline__ float gelu_exact(float x) {
    return 0.5f * x * (1.0f + erff(x * 0.7071067811865475f));
}

// ---------------- kernel 1: g-MLP for x / pos / neg ----------------
// grid 3*64 blocks (8 rows each), 256 threads
__global__ void __launch_bounds__(256) k_g_mlp(
    const float* __restrict__ fx, const float* __restrict__ fp, const float* __restrict__ fn,
    const float* __restrict__ w1, const float* __restrict__ b1,
    const float* __restrict__ w2, const float* __restrict__ b2)
{
    int bid = blockIdx.x;
    int mi = bid / 64;
    int r0 = (bid % 64) * 8;
    const float* X = (mi == 0) ? fx : (mi == 1 ? fp : fn);

    __shared__ float xs[8][D];   // 16 KB
    __shared__ float hs[8][HG];  // 8 KB
    int tid = threadIdx.x;

    for (int i = tid; i < 8 * D; i += 256)
        xs[i / D][i % D] = X[(r0 + i / D) * D + (i % D)];
    __syncthreads();

    int j = tid;  // 0..255 (hidden / rep column)
    float acc[8];
#pragma unroll
    for (int r = 0; r < 8; r++) acc[r] = 0.f;
    for (int k = 0; k < D; k++) {
        float wv = w1[k * HG + j];
#pragma unroll
        for (int r = 0; r < 8; r++) acc[r] += xs[r][k] * wv;
    }
    float bb = b1[j];
#pragma unroll
    for (int r = 0; r < 8; r++) hs[r][j] = gelu_exact(acc[r] + bb);
    __syncthreads();

    float a2[8];
#pragma unroll
    for (int r = 0; r < 8; r++) a2[r] = 0.f;
    for (int k = 0; k < HG; k++) {
        float wv = w2[k * R + j];
#pragma unroll
        for (int r = 0; r < 8; r++) a2[r] += hs[r][k] * wv;
    }
    float b2v = b2[j];
#pragma unroll
    for (int r = 0; r < 8; r++) d_rep[mi][r0 + r][j] = a2[r] + b2v;
}

// ---------------- kernel 2: squared norms ----------------
// grid 192 blocks * 256 threads, one warp per row (1536 rows)
__global__ void __launch_bounds__(256) k_norms() {
    int row = blockIdx.x * 8 + (threadIdx.x >> 5);  // 0..1535
    int mi = row / N, r = row % N;
    int lane = threadIdx.x & 31;
    float s = 0.f;
    for (int k = lane; k < R; k += 32) {
        float v = d_rep[mi][r][k];
        s += v * v;
    }
#pragma unroll
    for (int o = 16; o; o >>= 1) s += __shfl_xor_sync(0xFFFFFFFFu, s, o);
    if (lane == 0) d_norm2[mi][r] = s;
}

// ---------------- kernel 3: combined score weights ----------------
__global__ void k_wcomb(const float* __restrict__ s_w1) {
    int i = blockIdx.x * 256 + threadIdx.x;  // 0..32767
    if (i < R * H) {
        float wd = s_w1[2 * R * H + i];
        d_Wxd[i] = s_w1[i] - wd;
        d_Wyd[i] = s_w1[R * H + i] + wd;
    }
}

// ---------------- kernel 4: A and Bt ----------------
// grid 3*64 blocks (8 rows each), 128 threads
__global__ void __launch_bounds__(128) k_AB(const float* __restrict__ s_b1) {
    int bid = blockIdx.x;
    int mi = bid / 64;
    int r0 = (bid % 64) * 8;
    __shared__ float ys[8][R];  // 8 KB
    int tid = threadIdx.x;
    for (int i = tid; i < 8 * R; i += 128)
        ys[i / R][i % R] = d_rep[mi][r0 + i / R][i % R];
    __syncthreads();

    const float* Wc = (mi == 0) ? d_Wxd : d_Wyd;
    float acc[8];
#pragma unroll
    for (int r = 0; r < 8; r++) acc[r] = 0.f;
    for (int k = 0; k < R; k++) {
        float wv = Wc[k * H + tid];
#pragma unroll
        for (int r = 0; r < 8; r++) acc[r] += ys[r][k] * wv;
    }
    if (mi == 0) {
        float bb = s_b1[tid];
#pragma unroll
        for (int r = 0; r < 8; r++) d_A[(r0 + r) * H + tid] = acc[r] + bb;
    } else {
#pragma unroll
        for (int r = 0; r < 8; r++) d_Bt[mi - 1][tid * M + (r0 + r)] = acc[r];
    }
}

// ---------------- kernel 5: Gram matrices ----------------
// grid 2*256 blocks (32x32 tiles), 256 threads
__global__ void __launch_bounds__(256) k_gram() {
    int bid = blockIdx.x;
    int set = bid >> 8;
    int tt = bid & 255;
    int bn = (tt >> 4) * 32;
    int bm = (tt & 15) * 32;
    __shared__ float xs[32][32];
    __shared__ float yt[32][33];
    int tid = threadIdx.x;
    int li = tid >> 5;   // 0..7
    int lj = tid & 31;

    float acc[4] = {0.f, 0.f, 0.f, 0.f};
    for (int kc = 0; kc < R / 32; kc++) {
        __syncthreads();
#pragma unroll
        for (int p = 0; p < 4; p++) {
            int i = li + 8 * p;
            xs[i][lj] = d_rep[0][bn + i][kc * 32 + lj];
            yt[lj][i] = d_rep[set + 1][bm + i][kc * 32 + lj];
        }
        __syncthreads();
#pragma unroll
        for (int k = 0; k < 32; k++) {
            float yv = yt[k][lj];
#pragma unroll
            for (int p = 0; p < 4; p++) acc[p] += xs[li + 8 * p][k] * yv;
        }
    }
#pragma unroll
    for (int p = 0; p < 4; p++)
        d_G[set][(bn + li + 8 * p) * M + bm + lj] = acc[p];
}

// ---------------- kernel 6: score + softmax (the hot kernel) ----------------
// grid 2*64 blocks (8 n-rows each), 256 threads; each thread handles 2 m columns for all 8 n
__global__ void __launch_bounds__(256) k_score(
    const float* __restrict__ s_w1, const float* __restrict__ s_w2)
{
    int set = blockIdx.x >> 6;
    int n0 = (blockIdx.x & 63) * 8;
    __shared__ float As[8][H];       // 4 KB
    __shared__ float wn_s[H];
    __shared__ float s2_s[H];
    __shared__ float logits[8][M];   // 16 KB
    __shared__ float nxs[8];

    int tid = threadIdx.x;
    for (int i = tid; i < 8 * H; i += 256)
        As[i / H][i % H] = d_A[(n0 + i / H) * H + (i % H)];
    if (tid < H) {
        wn_s[tid] = s_w1[(3 * R) * H + tid];  // row 768 = Wn
        s2_s[tid] = s_w2[tid];
    }
    if (tid < 8) nxs[tid] = d_norm2[0][n0 + tid];
    __syncthreads();

    int m0 = tid, m1 = tid + 256;
    float ny0 = d_norm2[set + 1][m0];
    float ny1 = d_norm2[set + 1][m1];
    float t[8][2];
#pragma unroll
    for (int r = 0; r < 8; r++) {
        float g0 = d_G[set][(n0 + r) * M + m0];
        float g1 = d_G[set][(n0 + r) * M + m1];
        t[r][0] = sqrtf(fmaxf(nxs[r] + ny0 - 2.f * g0, 0.f));
        t[r][1] = sqrtf(fmaxf(nxs[r] + ny1 - 2.f * g1, 0.f));
    }

    float acc[8][2];
#pragma unroll
    for (int r = 0; r < 8; r++) { acc[r][0] = 0.f; acc[r][1] = 0.f; }

    const float* Bt = d_Bt[set];
#pragma unroll 2
    for (int k = 0; k < H; k++) {
        float wk = wn_s[k];
        float s2 = s2_s[k];
        float bv0 = Bt[k * M + m0];
        float bv1 = Bt[k * M + m1];
#pragma unroll
        for (int r = 0; r < 8; r++) {
            float a = As[r][k];
            float p0 = a + bv0 + t[r][0] * wk;
            float p1 = a + bv1 + t[r][1] * wk;
            acc[r][0] += gelu_exact(p0) * s2;
            acc[r][1] += gelu_exact(p1) * s2;
        }
    }
#pragma unroll
    for (int r = 0; r < 8; r++) {
        logits[r][m0] = acc[r][0];
        logits[r][m1] = acc[r][1];
    }
    __syncthreads();

    // softmax: warp w handles row w
    int w = tid >> 5, lane = tid & 31;
    float mx = -1e30f;
    for (int i = lane; i < M; i += 32) mx = fmaxf(mx, logits[w][i]);
#pragma unroll
    for (int o = 16; o; o >>= 1) mx = fmaxf(mx, __shfl_xor_sync(0xFFFFFFFFu, mx, o));
    float s = 0.f;
    for (int i = lane; i < M; i += 32) {
        float e = __expf(logits[w][i] - mx);
        logits[w][i] = e;
        s += e;
    }
#pragma unroll
    for (int o = 16; o; o >>= 1) s += __shfl_xor_sync(0xFFFFFFFFu, s, o);
    float inv = 1.f / s;
    for (int i = lane; i < M; i += 32)
        d_W[set][(n0 + w) * M + i] = logits[w][i] * inv;
}

// ---------------- kernel 7: Ud = W_pos @ pos_rep - W_neg @ neg_rep ----------------
// grid 64 blocks (8 rows), 256 threads (rep column)
__global__ void __launch_bounds__(256) k_u() {
    int n0 = blockIdx.x * 8;
    __shared__ float wp[8][M];  // 16 KB
    __shared__ float wq[8][M];  // 16 KB
    int tid = threadIdx.x;
    for (int i = tid; i < 8 * M; i += 256) {
        int r = i / M, m = i % M;
        wp[r][m] = d_W[0][(n0 + r) * M + m];
        wq[r][m] = d_W[1][(n0 + r) * M + m];
    }
    __syncthreads();
    float acc[8];
#pragma unroll
    for (int r = 0; r < 8; r++) acc[r] = 0.f;
    for (int m = 0; m < M; m++) {
        float yp = d_rep[1][m][tid];
        float yn = d_rep[2][m][tid];
#pragma unroll
        for (int r = 0; r < 8; r++) acc[r] += wp[r][m] * yp - wq[r][m] * yn;
    }
#pragma unroll
    for (int r = 0; r < 8; r++) d_Ud[(n0 + r) * R + tid] = acc[r];
}

// ---------------- kernel 8: out = Ud @ out_w ----------------
// grid 64 blocks (8 rows), 256 threads, 2 output cols each
__global__ void __launch_bounds__(256) k_out(const float* __restrict__ out_w,
                                             float* __restrict__ out)
{
    int n0 = blockIdx.x * 8;
    int tid = threadIdx.x;
    __shared__ float us[8][R];  // 8 KB
    for (int i = tid; i < 8 * R; i += 256)
        us[i / R][i % R] = d_Ud[(n0 + i / R) * R + (i % R)];
    __syncthreads();
    float a0[8], a1[8];
#pragma unroll
    for (int r = 0; r < 8; r++) { a0[r] = 0.f; a1[r] = 0.f; }
    for (int k = 0; k < R; k++) {
        float w0 = out_w[k * D + tid];
        float w1 = out_w[k * D + tid + 256];
#pragma unroll
        for (int r = 0; r < 8; r++) {
            a0[r] += us[r][k] * w0;
            a1[r] += us[r][k] * w1;
        }
    }
#pragma unroll
    for (int r = 0; r < 8; r++) {
        out[(n0 + r) * D + tid] = a0[r];
        out[(n0 + r) * D + tid + 256] = a1[r];
    }
}

// ---------------- launch ----------------
extern "C" void kernel_launch(void* const* d_in, const int* in_sizes, int n_in,
                              void* d_out, int out_size)
{
    const float* feat_x  = (const float*)d_in[0];
    const float* feat_pos= (const float*)d_in[1];
    const float* feat_neg= (const float*)d_in[2];
    const float* g_w1    = (const float*)d_in[3];
    const float* g_b1    = (const float*)d_in[4];
    const float* g_w2    = (const float*)d_in[5];
    const float* g_b2    = (const float*)d_in[6];
    const float* out_w   = (const float*)d_in[7];
    const float* s_w1    = (const float*)d_in[8];
    const float* s_b1    = (const float*)d_in[9];
    const float* s_w2    = (const float*)d_in[10];
    // d_in[11] = s_b2: constant shift, cancels in softmax — unused.
    float* out = (float*)d_out;
    (void)in_sizes; (void)n_in; (void)out_size;

    k_g_mlp<<<192, 256>>>(feat_x, feat_pos, feat_neg, g_w1, g_b1, g_w2, g_b2);
    k_norms<<<192, 256>>>();
    k_wcomb<<<128, 256>>>(s_w1);
    k_AB<<<192, 128>>>(s_b1);
    k_gram<<<512, 256>>>();
    k_score<<<128, 256>>>(s_w1, s_w2);
    k_u<<<64, 256>>>();
    k_out<<<64, 256>>>(out_w, out);
}

// round 2
// speedup vs baseline: 1.4261x; 1.4261x over previous
#include <cuda_runtime.h>
#include <math.h>

#define N 512
#define M 512
#define D 512
#define HG 256
#define R 256
#define H 128

// ---------------- device scratch ----------------
__device__ float d_rep[3][N][R];
__device__ float d_norm2[3][N];
__device__ float d_Wxd[R * H];
__device__ float d_Wyd[R * H];
__device__ float d_A[N * H];
__device__ float d_Bt[2][H * M];
__device__ float d_G[2][N * M];
__device__ float d_W[2][N * M];

__device__ __forceinline__ float gelu_exact(float x) {
    return 0.5f * x * (1.0f + erff(x * 0.7071067811865475f));
}

// ================= K1: g-MLP (+ row norms) and Wxd/Wyd combine =================
// grid = 192 mlp blocks (8 rows each) + 32 wcomb blocks, 256 threads
__global__ void __launch_bounds__(256) k1_gmlp(
    const float* __restrict__ fx, const float* __restrict__ fp, const float* __restrict__ fn,
    const float* __restrict__ w1, const float* __restrict__ b1,
    const float* __restrict__ w2, const float* __restrict__ b2,
    const float* __restrict__ s_w1)
{
    int bid = blockIdx.x;
    int tid = threadIdx.x;

    if (bid >= 192) {
        // weight-combine blocks: 32 blocks * 256 threads * 4
        int i0 = (bid - 192) * 1024 + tid;
#pragma unroll
        for (int t = 0; t < 4; t++) {
            int i = i0 + t * 256;
            float wd = s_w1[2 * R * H + i];
            d_Wxd[i] = s_w1[i] - wd;
            d_Wyd[i] = s_w1[R * H + i] + wd;
        }
        return;
    }

    int mi = bid / 64;
    int r0 = (bid % 64) * 8;
    const float* X = (mi == 0) ? fx : (mi == 1 ? fp : fn);

    __shared__ float xs[8][D];   // 16 KB
    __shared__ float hs[8][HG];  // 8 KB
    __shared__ float wsum[8][8];

    for (int i = tid; i < 8 * D; i += 256)
        xs[i / D][i % D] = X[(r0 + i / D) * D + (i % D)];
    __syncthreads();

    int j = tid;
    float acc[8];
#pragma unroll
    for (int r = 0; r < 8; r++) acc[r] = 0.f;
#pragma unroll 4
    for (int k = 0; k < D; k++) {
        float wv = w1[k * HG + j];
#pragma unroll
        for (int r = 0; r < 8; r++) acc[r] += xs[r][k] * wv;
    }
    float bb = b1[j];
#pragma unroll
    for (int r = 0; r < 8; r++) hs[r][j] = gelu_exact(acc[r] + bb);
    __syncthreads();

    float a2[8];
#pragma unroll
    for (int r = 0; r < 8; r++) a2[r] = 0.f;
#pragma unroll 4
    for (int k = 0; k < HG; k++) {
        float wv = w2[k * R + j];
#pragma unroll
        for (int r = 0; r < 8; r++) a2[r] += hs[r][k] * wv;
    }
    float b2v = b2[j];
    int w = tid >> 5, lane = tid & 31;
#pragma unroll
    for (int r = 0; r < 8; r++) {
        float v = a2[r] + b2v;
        d_rep[mi][r0 + r][j] = v;
        float s = v * v;
#pragma unroll
        for (int o = 16; o; o >>= 1) s += __shfl_xor_sync(0xFFFFFFFFu, s, o);
        if (lane == 0) wsum[w][r] = s;
    }
    __syncthreads();
    if (tid < 8) {
        float s = 0.f;
#pragma unroll
        for (int ww = 0; ww < 8; ww++) s += wsum[ww][tid];
        d_norm2[mi][r0 + tid] = s;
    }
}

// ================= K2: Gram (64x64 tiles) + A/Bt (split-K) =================
// grid = 128 gram blocks + 192 AB blocks, 256 threads
__global__ void __launch_bounds__(256) k2_gram_ab(const float* __restrict__ s_b1)
{
    __shared__ float smbuf[2 * 32 * 68];  // 17.4 KB, reused by both paths
    int bid = blockIdx.x;
    int tid = threadIdx.x;

    if (bid < 128) {
        // ---- Gram: G[set] = x_rep @ y_rep^T, 64x64 tile, 4x4 micro-tile ----
        int set = bid >> 6;
        int tt = bid & 63;
        int bn = (tt >> 3) * 64;
        int bm = (tt & 7) * 64;
        float (*xs)[68]  = (float(*)[68])smbuf;
        float (*ysm)[68] = (float(*)[68])(smbuf + 32 * 68);
        int ty = tid >> 4, tx = tid & 15;

        float acc[4][4];
#pragma unroll
        for (int i = 0; i < 4; i++)
#pragma unroll
            for (int jj = 0; jj < 4; jj++) acc[i][jj] = 0.f;

        for (int kc = 0; kc < R / 32; kc++) {
            __syncthreads();
#pragma unroll
            for (int p = 0; p < 8; p++) {
                int i = tid + p * 256;
                int n = i >> 5, k = i & 31;
                xs[k][n]  = d_rep[0][bn + n][kc * 32 + k];
                ysm[k][n] = d_rep[set + 1][bm + n][kc * 32 + k];
            }
            __syncthreads();
#pragma unroll
            for (int k = 0; k < 32; k++) {
                float4 xv = *(const float4*)&xs[k][ty * 4];
                float4 yv = *(const float4*)&ysm[k][tx * 4];
                float xa[4] = {xv.x, xv.y, xv.z, xv.w};
                float ya[4] = {yv.x, yv.y, yv.z, yv.w};
#pragma unroll
                for (int i = 0; i < 4; i++)
#pragma unroll
                    for (int jj = 0; jj < 4; jj++) acc[i][jj] += xa[i] * ya[jj];
            }
        }
#pragma unroll
        for (int i = 0; i < 4; i++) {
            float4 o = make_float4(acc[i][0], acc[i][1], acc[i][2], acc[i][3]);
            *(float4*)&d_G[set][(bn + ty * 4 + i) * M + bm + tx * 4] = o;
        }
    } else {
        // ---- A / Bt: 8 rows/block, split-K over 2 halves ----
        int ab = bid - 128;
        int mi = ab / 64;
        int r0 = (ab % 64) * 8;
        float (*ys)[R] = (float(*)[R])smbuf;            // [8][256] = 8KB
        float (*ps)[H] = (float(*)[H])(smbuf + 8 * R);  // [8][128] = 4KB

        for (int i = tid; i < 8 * R; i += 256)
            ys[i / R][i % R] = d_rep[mi][r0 + i / R][i % R];
        __syncthreads();

        int h = tid & 127;
        int half = tid >> 7;
        const float* Wc = (mi == 0) ? d_Wxd : d_Wyd;
        float acc[8];
#pragma unroll
        for (int r = 0; r < 8; r++) acc[r] = 0.f;
        int kbeg = half * 128;
#pragma unroll 4
        for (int k = kbeg; k < kbeg + 128; k++) {
            float wv = Wc[k * H + h];
#pragma unroll
            for (int r = 0; r < 8; r++) acc[r] += ys[r][k] * wv;
        }
        if (half == 1) {
#pragma unroll
            for (int r = 0; r < 8; r++) ps[r][h] = acc[r];
        }
        __syncthreads();
        if (half == 0) {
            if (mi == 0) {
                float bb = s_b1[h];
#pragma unroll
                for (int r = 0; r < 8; r++)
                    d_A[(r0 + r) * H + h] = acc[r] + ps[r][h] + bb;
            } else {
#pragma unroll
                for (int r = 0; r < 8; r++)
                    d_Bt[mi - 1][h * M + (r0 + r)] = acc[r] + ps[r][h];
            }
        }
    }
}

// ================= K3: score + softmax (hot) =================
// grid = 2 sets * 256 (2 n-rows each) = 512 blocks, 256 threads
__global__ void __launch_bounds__(256) k3_score(
    const float* __restrict__ s_w1, const float* __restrict__ s_w2)
{
    int set = blockIdx.x >> 8;
    int n0 = (blockIdx.x & 255) * 2;
    __shared__ float As[2][H];
    __shared__ float wn_s[H];
    __shared__ float s2_s[H];
    __shared__ float logits[2][M];
    __shared__ float nxs[2];
    __shared__ float red[2][8];

    int tid = threadIdx.x;
    if (tid < 2 * H) As[tid >> 7][tid & 127] = d_A[(n0 + (tid >> 7)) * H + (tid & 127)];
    if (tid >= 2 * H) {
        int q = tid - 2 * H;  // 0..127? no: 256-256=0.. careful
    }
    // separate loads (256 threads): As needs 256 loads exactly
    if (tid < H) {
        wn_s[tid] = s_w1[(3 * R) * H + tid];
        s2_s[tid] = s_w2[tid];
    }
    if (tid < 2) nxs[tid] = d_norm2[0][n0 + tid];
    __syncthreads();

    int m0 = tid, m1 = tid + 256;
    float ny0 = d_norm2[set + 1][m0];
    float ny1 = d_norm2[set + 1][m1];
    float t[2][2];
#pragma unroll
    for (int r = 0; r < 2; r++) {
        float g0 = d_G[set][(n0 + r) * M + m0];
        float g1 = d_G[set][(n0 + r) * M + m1];
        t[r][0] = sqrtf(fmaxf(nxs[r] + ny0 - 2.f * g0, 0.f));
        t[r][1] = sqrtf(fmaxf(nxs[r] + ny1 - 2.f * g1, 0.f));
    }

    float acc00 = 0.f, acc01 = 0.f, acc10 = 0.f, acc11 = 0.f;
    const float* Bt = d_Bt[set];
#pragma unroll 4
    for (int k = 0; k < H; k++) {
        float wk = wn_s[k];
        float s2 = s2_s[k];
        float bv0 = Bt[k * M + m0];
        float bv1 = Bt[k * M + m1];
        float a0 = As[0][k], a1 = As[1][k];
        acc00 += gelu_exact(a0 + bv0 + t[0][0] * wk) * s2;
        acc01 += gelu_exact(a0 + bv1 + t[0][1] * wk) * s2;
        acc10 += gelu_exact(a1 + bv0 + t[1][0] * wk) * s2;
        acc11 += gelu_exact(a1 + bv1 + t[1][1] * wk) * s2;
    }
    logits[0][m0] = acc00; logits[0][m1] = acc01;
    logits[1][m0] = acc10; logits[1][m1] = acc11;
    __syncthreads();

    // softmax: 128 threads per row
    int row = tid >> 7;
    int c = tid & 127;
    int w4 = (tid >> 5) & 3;  // warp within row group
    int lane = tid & 31;
    float v0 = logits[row][c], v1 = logits[row][c + 128];
    float v2 = logits[row][c + 256], v3 = logits[row][c + 384];
    float mx = fmaxf(fmaxf(v0, v1), fmaxf(v2, v3));
#pragma unroll
    for (int o = 16; o; o >>= 1) mx = fmaxf(mx, __shfl_xor_sync(0xFFFFFFFFu, mx, o));
    if (lane == 0) red[row][w4] = mx;
    __syncthreads();
    mx = fmaxf(fmaxf(red[row][0], red[row][1]), fmaxf(red[row][2], red[row][3]));
    float e0 = __expf(v0 - mx), e1 = __expf(v1 - mx);
    float e2 = __expf(v2 - mx), e3 = __expf(v3 - mx);
    float s = e0 + e1 + e2 + e3;
#pragma unroll
    for (int o = 16; o; o >>= 1) s += __shfl_xor_sync(0xFFFFFFFFu, s, o);
    __syncthreads();
    if (lane == 0) red[row][w4 + 4] = s;
    __syncthreads();
    s = red[row][4] + red[row][5] + red[row][6] + red[row][7];
    float inv = 1.f / s;
    float* Wrow = &d_W[set][(n0 + row) * M];
    Wrow[c] = e0 * inv; Wrow[c + 128] = e1 * inv;
    Wrow[c + 256] = e2 * inv; Wrow[c + 384] = e3 * inv;
}

// ================= K4: U = W_pos@pos - W_neg@neg ; out = U @ out_w =================
// grid = 128 blocks (4 rows each), 256 threads
__global__ void __launch_bounds__(256) k4_u_out(const float* __restrict__ out_w,
                                                float* __restrict__ out)
{
    int n0 = blockIdx.x * 4;
    int tid = threadIdx.x;
    __shared__ float wp[4][M];   // 8 KB
    __shared__ float wq[4][M];   // 8 KB
    __shared__ float us[4][R];   // 4 KB

    for (int i = tid; i < 4 * M; i += 256) {
        int r = i / M, m = i % M;
        wp[r][m] = d_W[0][(n0 + r) * M + m];
        wq[r][m] = d_W[1][(n0 + r) * M + m];
    }
    __syncthreads();

    float acc[4];
#pragma unroll
    for (int r = 0; r < 4; r++) acc[r] = 0.f;
#pragma unroll 4
    for (int m = 0; m < M; m++) {
        float yp = d_rep[1][m][tid];
        float yn = d_rep[2][m][tid];
#pragma unroll
        for (int r = 0; r < 4; r++) acc[r] += wp[r][m] * yp - wq[r][m] * yn;
    }
#pragma unroll
    for (int r = 0; r < 4; r++) us[r][tid] = acc[r];
    __syncthreads();

    float a0[4], a1[4];
#pragma unroll
    for (int r = 0; r < 4; r++) { a0[r] = 0.f; a1[r] = 0.f; }
#pragma unroll 4
    for (int k = 0; k < R; k++) {
        float w0 = out_w[k * D + tid];
        float w1 = out_w[k * D + tid + 256];
#pragma unroll
        for (int r = 0; r < 4; r++) {
            a0[r] += us[r][k] * w0;
            a1[r] += us[r][k] * w1;
        }
    }
#pragma unroll
    for (int r = 0; r < 4; r++) {
        out[(n0 + r) * D + tid] = a0[r];
        out[(n0 + r) * D + tid + 256] = a1[r];
    }
}

// ---------------- launch ----------------
extern "C" void kernel_launch(void* const* d_in, const int* in_sizes, int n_in,
                              void* d_out, int out_size)
{
    const float* feat_x  = (const float*)d_in[0];
    const float* feat_pos= (const float*)d_in[1];
    const float* feat_neg= (const float*)d_in[2];
    const float* g_w1    = (const float*)d_in[3];
    const float* g_b1    = (const float*)d_in[4];
    const float* g_w2    = (const float*)d_in[5];
    const float* g_b2    = (const float*)d_in[6];
    const float* out_w   = (const float*)d_in[7];
    const float* s_w1    = (const float*)d_in[8];
    const float* s_b1    = (const float*)d_in[9];
    const float* s_w2    = (const float*)d_in[10];
    float* out = (float*)d_out;
    (void)in_sizes; (void)n_in; (void)out_size;

    k1_gmlp<<<224, 256>>>(feat_x, feat_pos, feat_neg, g_w1, g_b1, g_w2, g_b2, s_w1);
    k2_gram_ab<<<320, 256>>>(s_b1);
    k3_score<<<512, 256>>>(s_w1, s_w2);
    k4_u_out<<<128, 256>>>(out_w, out);
}

// round 3
// speedup vs baseline: 1.5197x; 1.0656x over previous
#include <cuda_runtime.h>
#include <math.h>

#define N 512
#define M 512
#define D 512
#define HG 256
#define R 256
#define H 128

// ---------------- device scratch ----------------
__device__ float d_rep[3][N][R];
__device__ float d_norm2[3][N];
__device__ float d_Wxd[R * H];
__device__ float d_Wyd[R * H];
__device__ float d_A[N * H];        // pre-scaled by 1/sqrt(2)
__device__ float d_Bt[2][H * M];    // pre-scaled by 1/sqrt(2)
__device__ float d_G[2][N * M];
__device__ float d_W[2][N * M];
__device__ float d_U[N * R];

#define INV_SQRT2 0.7071067811865476f

__device__ __forceinline__ float gelu_exact(float x) {
    return 0.5f * x * (1.0f + erff(x * INV_SQRT2));
}

// ================= K1: g-MLP (+ row norms) and Wxd/Wyd combine =================
__global__ void __launch_bounds__(256) k1_gmlp(
    const float* __restrict__ fx, const float* __restrict__ fp, const float* __restrict__ fn,
    const float* __restrict__ w1, const float* __restrict__ b1,
    const float* __restrict__ w2, const float* __restrict__ b2,
    const float* __restrict__ s_w1)
{
    int bid = blockIdx.x;
    int tid = threadIdx.x;

    if (bid >= 192) {
        int i0 = (bid - 192) * 1024 + tid;
#pragma unroll
        for (int t = 0; t < 4; t++) {
            int i = i0 + t * 256;
            float wd = s_w1[2 * R * H + i];
            d_Wxd[i] = s_w1[i] - wd;
            d_Wyd[i] = s_w1[R * H + i] + wd;
        }
        return;
    }

    int mi = bid / 64;
    int r0 = (bid % 64) * 8;
    const float* X = (mi == 0) ? fx : (mi == 1 ? fp : fn);

    __shared__ float xs[8][D];
    __shared__ float hs[8][HG];
    __shared__ float wsum[8][8];

    for (int i = tid; i < 8 * D; i += 256)
        xs[i / D][i % D] = X[(r0 + i / D) * D + (i % D)];
    __syncthreads();

    int j = tid;
    float acc[8];
#pragma unroll
    for (int r = 0; r < 8; r++) acc[r] = 0.f;
#pragma unroll 4
    for (int k = 0; k < D; k++) {
        float wv = w1[k * HG + j];
#pragma unroll
        for (int r = 0; r < 8; r++) acc[r] += xs[r][k] * wv;
    }
    float bb = b1[j];
#pragma unroll
    for (int r = 0; r < 8; r++) hs[r][j] = gelu_exact(acc[r] + bb);
    __syncthreads();

    float a2[8];
#pragma unroll
    for (int r = 0; r < 8; r++) a2[r] = 0.f;
#pragma unroll 4
    for (int k = 0; k < HG; k++) {
        float wv = w2[k * R + j];
#pragma unroll
        for (int r = 0; r < 8; r++) a2[r] += hs[r][k] * wv;
    }
    float b2v = b2[j];
    int w = tid >> 5, lane = tid & 31;
#pragma unroll
    for (int r = 0; r < 8; r++) {
        float v = a2[r] + b2v;
        d_rep[mi][r0 + r][j] = v;
        float s = v * v;
#pragma unroll
        for (int o = 16; o; o >>= 1) s += __shfl_xor_sync(0xFFFFFFFFu, s, o);
        if (lane == 0) wsum[w][r] = s;
    }
    __syncthreads();
    if (tid < 8) {
        float s = 0.f;
#pragma unroll
        for (int ww = 0; ww < 8; ww++) s += wsum[ww][tid];
        d_norm2[mi][r0 + tid] = s;
    }
}

// ================= K2: Gram (64x64) + A/Bt (split-K, scaled by 1/sqrt2) =================
__global__ void __launch_bounds__(256) k2_gram_ab(const float* __restrict__ s_b1)
{
    __shared__ float smbuf[2 * 32 * 68];
    int bid = blockIdx.x;
    int tid = threadIdx.x;

    if (bid < 128) {
        int set = bid >> 6;
        int tt = bid & 63;
        int bn = (tt >> 3) * 64;
        int bm = (tt & 7) * 64;
        float (*xs)[68]  = (float(*)[68])smbuf;
        float (*ysm)[68] = (float(*)[68])(smbuf + 32 * 68);
        int ty = tid >> 4, tx = tid & 15;

        float acc[4][4];
#pragma unroll
        for (int i = 0; i < 4; i++)
#pragma unroll
            for (int jj = 0; jj < 4; jj++) acc[i][jj] = 0.f;

        for (int kc = 0; kc < R / 32; kc++) {
            __syncthreads();
#pragma unroll
            for (int p = 0; p < 8; p++) {
                int i = tid + p * 256;
                int n = i >> 5, k = i & 31;
                xs[k][n]  = d_rep[0][bn + n][kc * 32 + k];
                ysm[k][n] = d_rep[set + 1][bm + n][kc * 32 + k];
            }
            __syncthreads();
#pragma unroll
            for (int k = 0; k < 32; k++) {
                float4 xv = *(const float4*)&xs[k][ty * 4];
                float4 yv = *(const float4*)&ysm[k][tx * 4];
                float xa[4] = {xv.x, xv.y, xv.z, xv.w};
                float ya[4] = {yv.x, yv.y, yv.z, yv.w};
#pragma unroll
                for (int i = 0; i < 4; i++)
#pragma unroll
                    for (int jj = 0; jj < 4; jj++) acc[i][jj] += xa[i] * ya[jj];
            }
        }
#pragma unroll
        for (int i = 0; i < 4; i++) {
            float4 o = make_float4(acc[i][0], acc[i][1], acc[i][2], acc[i][3]);
            *(float4*)&d_G[set][(bn + ty * 4 + i) * M + bm + tx * 4] = o;
        }
    } else {
        int ab = bid - 128;
        int mi = ab / 64;
        int r0 = (ab % 64) * 8;
        float (*ys)[R] = (float(*)[R])smbuf;
        float (*ps)[H] = (float(*)[H])(smbuf + 8 * R);

        for (int i = tid; i < 8 * R; i += 256)
            ys[i / R][i % R] = d_rep[mi][r0 + i / R][i % R];
        __syncthreads();

        int h = tid & 127;
        int half = tid >> 7;
        const float* Wc = (mi == 0) ? d_Wxd : d_Wyd;
        float acc[8];
#pragma unroll
        for (int r = 0; r < 8; r++) acc[r] = 0.f;
        int kbeg = half * 128;
#pragma unroll 4
        for (int k = kbeg; k < kbeg + 128; k++) {
            float wv = Wc[k * H + h];
#pragma unroll
            for (int r = 0; r < 8; r++) acc[r] += ys[r][k] * wv;
        }
        if (half == 1) {
#pragma unroll
            for (int r = 0; r < 8; r++) ps[r][h] = acc[r];
        }
        __syncthreads();
        if (half == 0) {
            if (mi == 0) {
                float bb = s_b1[h];
#pragma unroll
                for (int r = 0; r < 8; r++)
                    d_A[(r0 + r) * H + h] = (acc[r] + ps[r][h] + bb) * INV_SQRT2;
            } else {
#pragma unroll
                for (int r = 0; r < 8; r++)
                    d_Bt[mi - 1][h * M + (r0 + r)] = (acc[r] + ps[r][h]) * INV_SQRT2;
            }
        }
    }
}

// ================= K3: score + softmax (hot) =================
// pre-activation already scaled by 1/sqrt2; gelu*s2 = s2h * p' * (1+erf(p')),
// s2h = s_w2 * 0.5*sqrt(2)
__global__ void __launch_bounds__(256) k3_score(
    const float* __restrict__ s_w1, const float* __restrict__ s_w2)
{
    int set = blockIdx.x >> 8;
    int n0 = (blockIdx.x & 255) * 2;
    __shared__ float As[2][H];
    __shared__ float wn_s[H];
    __shared__ float s2h[H];
    __shared__ float logits[2][M];
    __shared__ float nxs[2];
    __shared__ float red[2][8];

    int tid = threadIdx.x;
    As[tid >> 7][tid & 127] = d_A[(n0 + (tid >> 7)) * H + (tid & 127)];
    if (tid < H) {
        wn_s[tid] = s_w1[(3 * R) * H + tid] * INV_SQRT2;
        s2h[tid]  = s_w2[tid] * 0.7071067811865476f;
    }
    if (tid < 2) nxs[tid] = d_norm2[0][n0 + tid];
    __syncthreads();

    int m0 = tid, m1 = tid + 256;
    float ny0 = d_norm2[set + 1][m0];
    float ny1 = d_norm2[set + 1][m1];
    float t00, t01, t10, t11;
    {
        float g00 = d_G[set][(n0 + 0) * M + m0];
        float g01 = d_G[set][(n0 + 0) * M + m1];
        float g10 = d_G[set][(n0 + 1) * M + m0];
        float g11 = d_G[set][(n0 + 1) * M + m1];
        t00 = sqrtf(fmaxf(nxs[0] + ny0 - 2.f * g00, 0.f));
        t01 = sqrtf(fmaxf(nxs[0] + ny1 - 2.f * g01, 0.f));
        t10 = sqrtf(fmaxf(nxs[1] + ny0 - 2.f * g10, 0.f));
        t11 = sqrtf(fmaxf(nxs[1] + ny1 - 2.f * g11, 0.f));
    }

    float acc00 = 0.f, acc01 = 0.f, acc10 = 0.f, acc11 = 0.f;
    const float* Bt = d_Bt[set];
#pragma unroll 4
    for (int k = 0; k < H; k++) {
        float wk = wn_s[k];
        float s2 = s2h[k];
        float bv0 = Bt[k * M + m0];
        float bv1 = Bt[k * M + m1];
        float a0 = As[0][k], a1 = As[1][k];
        float ab00 = a0 + bv0, ab01 = a0 + bv1;
        float ab10 = a1 + bv0, ab11 = a1 + bv1;
        float p00 = fmaf(t00, wk, ab00);
        float p01 = fmaf(t01, wk, ab01);
        float p10 = fmaf(t10, wk, ab10);
        float p11 = fmaf(t11, wk, ab11);
        float e00 = erff(p00), e01 = erff(p01);
        float e10 = erff(p10), e11 = erff(p11);
        float q00 = p00 * s2, q01 = p01 * s2;
        float q10 = p10 * s2, q11 = p11 * s2;
        acc00 = fmaf(q00, e00, acc00 + q00);
        acc01 = fmaf(q01, e01, acc01 + q01);
        acc10 = fmaf(q10, e10, acc10 + q10);
        acc11 = fmaf(q11, e11, acc11 + q11);
    }
    logits[0][m0] = acc00; logits[0][m1] = acc01;
    logits[1][m0] = acc10; logits[1][m1] = acc11;
    __syncthreads();

    int row = tid >> 7;
    int c = tid & 127;
    int w4 = (tid >> 5) & 3;
    int lane = tid & 31;
    float v0 = logits[row][c], v1 = logits[row][c + 128];
    float v2 = logits[row][c + 256], v3 = logits[row][c + 384];
    float mx = fmaxf(fmaxf(v0, v1), fmaxf(v2, v3));
#pragma unroll
    for (int o = 16; o; o >>= 1) mx = fmaxf(mx, __shfl_xor_sync(0xFFFFFFFFu, mx, o));
    if (lane == 0) red[row][w4] = mx;
    __syncthreads();
    mx = fmaxf(fmaxf(red[row][0], red[row][1]), fmaxf(red[row][2], red[row][3]));
    float e0 = __expf(v0 - mx), e1 = __expf(v1 - mx);
    float e2 = __expf(v2 - mx), e3 = __expf(v3 - mx);
    float s = e0 + e1 + e2 + e3;
#pragma unroll
    for (int o = 16; o; o >>= 1) s += __shfl_xor_sync(0xFFFFFFFFu, s, o);
    __syncthreads();
    if (lane == 0) red[row][w4 + 4] = s;
    __syncthreads();
    s = red[row][4] + red[row][5] + red[row][6] + red[row][7];
    float inv = 1.f / s;
    float* Wrow = &d_W[set][(n0 + row) * M];
    Wrow[c] = e0 * inv; Wrow[c + 128] = e1 * inv;
    Wrow[c + 256] = e2 * inv; Wrow[c + 384] = e3 * inv;
}

// ================= K4a: U = Wp @ Yp - Wq @ Yn (tiled GEMM) =================
// 32(n) x 64(r) tiles, grid 16x4 = 64 blocks, 256 threads, 2x4 micro
__global__ void __launch_bounds__(256) k4a_u()
{
    __shared__ float w_s[2][16][36];   // [set][kk][n]
    __shared__ float yp_s[16][64];
    __shared__ float yn_s[16][64];

    int bid = blockIdx.x;
    int bn = (bid >> 2) * 32;
    int br = (bid & 3) * 64;
    int tid = threadIdx.x;
    int ty = tid >> 4;       // 0..15 -> n = ty*2
    int tx = tid & 15;       // 0..15 -> r = tx*4

    // load indices
    int wset = tid >> 7;            // 0: wp, 1: wq
    int wn = (tid & 127) >> 2;      // 0..31
    int wm = (tid & 3) * 4;         // 0..12
    int ykk = tid >> 4;             // 0..15
    int yc = (tid & 15) * 4;

    float acc[2][4];
#pragma unroll
    for (int i = 0; i < 2; i++)
#pragma unroll
        for (int j = 0; j < 4; j++) acc[i][j] = 0.f;

    for (int mc = 0; mc < M / 16; mc++) {
        float4 wv = *(const float4*)&d_W[wset][(bn + wn) * M + mc * 16 + wm];
        float4 ypv = *(const float4*)&d_rep[1][mc * 16 + ykk][br + yc];
        float4 ynv = *(const float4*)&d_rep[2][mc * 16 + ykk][br + yc];
        __syncthreads();
        w_s[wset][wm + 0][wn] = wv.x;
        w_s[wset][wm + 1][wn] = wv.y;
        w_s[wset][wm + 2][wn] = wv.z;
        w_s[wset][wm + 3][wn] = wv.w;
        *(float4*)&yp_s[ykk][yc] = ypv;
        *(float4*)&yn_s[ykk][yc] = ynv;
        __syncthreads();
#pragma unroll
        for (int kk = 0; kk < 16; kk++) {
            float wp0 = w_s[0][kk][ty * 2], wp1 = w_s[0][kk][ty * 2 + 1];
            float wq0 = w_s[1][kk][ty * 2], wq1 = w_s[1][kk][ty * 2 + 1];
            float4 yp = *(const float4*)&yp_s[kk][tx * 4];
            float4 yn = *(const float4*)&yn_s[kk][tx * 4];
            float ypa[4] = {yp.x, yp.y, yp.z, yp.w};
            float yna[4] = {yn.x, yn.y, yn.z, yn.w};
#pragma unroll
            for (int j = 0; j < 4; j++) {
                acc[0][j] += wp0 * ypa[j];
                acc[1][j] += wp1 * ypa[j];
                acc[0][j] -= wq0 * yna[j];
                acc[1][j] -= wq1 * yna[j];
            }
        }
    }
#pragma unroll
    for (int i = 0; i < 2; i++) {
        float4 o = make_float4(acc[i][0], acc[i][1], acc[i][2], acc[i][3]);
        *(float4*)&d_U[(bn + ty * 2 + i) * R + br + tx * 4] = o;
    }
}

// ================= K4b: out = U @ out_w (tiled GEMM) =================
// 64x64 tiles, grid 8x8 = 64 blocks, 256 threads, 4x4 micro
__global__ void __launch_bounds__(256) k4b_out(const float* __restrict__ out_w,
                                               float* __restrict__ out)
{
    __shared__ float us[16][72];   // [kk][n]
    __shared__ float ws[16][64];   // [kk][d]

    int bid = blockIdx.x;
    int bn = (bid >> 3) * 64;
    int bd = (bid & 7) * 64;
    int tid = threadIdx.x;
    int ty = tid >> 4, tx = tid & 15;

    int un = tid >> 2;          // 0..63
    int uk = (tid & 3) * 4;     // 0..12
    int wkk = tid >> 4;         // 0..15
    int wc = (tid & 15) * 4;

    float acc[4][4];
#pragma unroll
    for (int i = 0; i < 4; i++)
#pragma unroll
        for (int j = 0; j < 4; j++) acc[i][j] = 0.f;

    for (int kc = 0; kc < R / 16; kc++) {
        float4 uv = *(const float4*)&d_U[(bn + un) * R + kc * 16 + uk];
        float4 wv = *(const float4*)&out_w[(kc * 16 + wkk) * D + bd + wc];
        __syncthreads();
        us[uk + 0][un] = uv.x;
        us[uk + 1][un] = uv.y;
        us[uk + 2][un] = uv.z;
        us[uk + 3][un] = uv.w;
        *(float4*)&ws[wkk][wc] = wv;
        __syncthreads();
#pragma unroll
        for (int kk = 0; kk < 16; kk++) {
            float ua[4];
#pragma unroll
            for (int i = 0; i < 4; i++) ua[i] = us[kk][ty * 4 + i];
            float4 w4 = *(const float4*)&ws[kk][tx * 4];
            float wa[4] = {w4.x, w4.y, w4.z, w4.w};
#pragma unroll
            for (int i = 0; i < 4; i++)
#pragma unroll
                for (int j = 0; j < 4; j++) acc[i][j] += ua[i] * wa[j];
        }
    }
#pragma unroll
    for (int i = 0; i < 4; i++) {
        float4 o = make_float4(acc[i][0], acc[i][1], acc[i][2], acc[i][3]);
        *(float4*)&out[(bn + ty * 4 + i) * D + bd + tx * 4] = o;
    }
}

// ---------------- launch ----------------
extern "C" void kernel_launch(void* const* d_in, const int* in_sizes, int n_in,
                              void* d_out, int out_size)
{
    const float* feat_x  = (const float*)d_in[0];
    const float* feat_pos= (const float*)d_in[1];
    const float* feat_neg= (const float*)d_in[2];
    const float* g_w1    = (const float*)d_in[3];
    const float* g_b1    = (const float*)d_in[4];
    const float* g_w2    = (const float*)d_in[5];
    const float* g_b2    = (const float*)d_in[6];
    const float* out_w   = (const float*)d_in[7];
    const float* s_w1    = (const float*)d_in[8];
    const float* s_b1    = (const float*)d_in[9];
    const float* s_w2    = (const float*)d_in[10];
    float* out = (float*)d_out;
    (void)in_sizes; (void)n_in; (void)out_size;

    k1_gmlp<<<224, 256>>>(feat_x, feat_pos, feat_neg, g_w1, g_b1, g_w2, g_b2, s_w1);
    k2_gram_ab<<<320, 256>>>(s_b1);
    k3_score<<<512, 256>>>(s_w1, s_w2);
    k4a_u<<<64, 256>>>();
    k4b_out<<<64, 256>>>(out_w, out);
}

// round 4
// speedup vs baseline: 1.7297x; 1.1382x over previous
#include <cuda_runtime.h>
#include <math.h>

#define N 512
#define M 512
#define D 512
#define HG 256
#define R 256
#define H 128

// ---------------- device scratch ----------------
__device__ float d_rep[3][N][R];
__device__ float d_norm2[3][N];
__device__ float d_Wxd[R * H];
__device__ float d_Wyd[R * H];
__device__ float d_A[N * H];        // pre-scaled by 1/sqrt(2)
__device__ float d_Bt[2][H * M];    // pre-scaled by 1/sqrt(2)
__device__ float d_G[2][N * M];
__device__ float d_W[2][N * M];
__device__ float d_Upart[4][N][R];  // split-K partials of U

#define INV_SQRT2 0.7071067811865476f

__device__ __forceinline__ float gelu_exact(float x) {
    return 0.5f * x * (1.0f + erff(x * INV_SQRT2));
}

// ================= K1: g-MLP (+ row norms) and Wxd/Wyd combine =================
__global__ void __launch_bounds__(256) k1_gmlp(
    const float* __restrict__ fx, const float* __restrict__ fp, const float* __restrict__ fn,
    const float* __restrict__ w1, const float* __restrict__ b1,
    const float* __restrict__ w2, const float* __restrict__ b2,
    const float* __restrict__ s_w1)
{
    int bid = blockIdx.x;
    int tid = threadIdx.x;

    if (bid >= 192) {
        int i0 = (bid - 192) * 1024 + tid;
#pragma unroll
        for (int t = 0; t < 4; t++) {
            int i = i0 + t * 256;
            float wd = s_w1[2 * R * H + i];
            d_Wxd[i] = s_w1[i] - wd;
            d_Wyd[i] = s_w1[R * H + i] + wd;
        }
        return;
    }

    int mi = bid / 64;
    int r0 = (bid % 64) * 8;
    const float* X = (mi == 0) ? fx : (mi == 1 ? fp : fn);

    __shared__ float xs[8][D];
    __shared__ float hs[8][HG];
    __shared__ float wsum[8][8];

    for (int i = tid; i < 8 * D; i += 256)
        xs[i / D][i % D] = X[(r0 + i / D) * D + (i % D)];
    __syncthreads();

    int j = tid;
    float acc[8];
#pragma unroll
    for (int r = 0; r < 8; r++) acc[r] = 0.f;
#pragma unroll 4
    for (int k = 0; k < D; k++) {
        float wv = w1[k * HG + j];
#pragma unroll
        for (int r = 0; r < 8; r++) acc[r] += xs[r][k] * wv;
    }
    float bb = b1[j];
#pragma unroll
    for (int r = 0; r < 8; r++) hs[r][j] = gelu_exact(acc[r] + bb);
    __syncthreads();

    float a2[8];
#pragma unroll
    for (int r = 0; r < 8; r++) a2[r] = 0.f;
#pragma unroll 4
    for (int k = 0; k < HG; k++) {
        float wv = w2[k * R + j];
#pragma unroll
        for (int r = 0; r < 8; r++) a2[r] += hs[r][k] * wv;
    }
    float b2v = b2[j];
    int w = tid >> 5, lane = tid & 31;
#pragma unroll
    for (int r = 0; r < 8; r++) {
        float v = a2[r] + b2v;
        d_rep[mi][r0 + r][j] = v;
        float s = v * v;
#pragma unroll
        for (int o = 16; o; o >>= 1) s += __shfl_xor_sync(0xFFFFFFFFu, s, o);
        if (lane == 0) wsum[w][r] = s;
    }
    __syncthreads();
    if (tid < 8) {
        float s = 0.f;
#pragma unroll
        for (int ww = 0; ww < 8; ww++) s += wsum[ww][tid];
        d_norm2[mi][r0 + tid] = s;
    }
}

// ================= K2: Gram (64x64) + A/Bt (split-K, scaled by 1/sqrt2) =================
__global__ void __launch_bounds__(256) k2_gram_ab(const float* __restrict__ s_b1)
{
    __shared__ float smbuf[2 * 32 * 68];
    int bid = blockIdx.x;
    int tid = threadIdx.x;

    if (bid < 128) {
        int set = bid >> 6;
        int tt = bid & 63;
        int bn = (tt >> 3) * 64;
        int bm = (tt & 7) * 64;
        float (*xs)[68]  = (float(*)[68])smbuf;
        float (*ysm)[68] = (float(*)[68])(smbuf + 32 * 68);
        int ty = tid >> 4, tx = tid & 15;

        float acc[4][4];
#pragma unroll
        for (int i = 0; i < 4; i++)
#pragma unroll
            for (int jj = 0; jj < 4; jj++) acc[i][jj] = 0.f;

        for (int kc = 0; kc < R / 32; kc++) {
            __syncthreads();
#pragma unroll
            for (int p = 0; p < 8; p++) {
                int i = tid + p * 256;
                int n = i >> 5, k = i & 31;
                xs[k][n]  = d_rep[0][bn + n][kc * 32 + k];
                ysm[k][n] = d_rep[set + 1][bm + n][kc * 32 + k];
            }
            __syncthreads();
#pragma unroll
            for (int k = 0; k < 32; k++) {
                float4 xv = *(const float4*)&xs[k][ty * 4];
                float4 yv = *(const float4*)&ysm[k][tx * 4];
                float xa[4] = {xv.x, xv.y, xv.z, xv.w};
                float ya[4] = {yv.x, yv.y, yv.z, yv.w};
#pragma unroll
                for (int i = 0; i < 4; i++)
#pragma unroll
                    for (int jj = 0; jj < 4; jj++) acc[i][jj] += xa[i] * ya[jj];
            }
        }
#pragma unroll
        for (int i = 0; i < 4; i++) {
            float4 o = make_float4(acc[i][0], acc[i][1], acc[i][2], acc[i][3]);
            *(float4*)&d_G[set][(bn + ty * 4 + i) * M + bm + tx * 4] = o;
        }
    } else {
        int ab = bid - 128;
        int mi = ab / 64;
        int r0 = (ab % 64) * 8;
        float (*ys)[R] = (float(*)[R])smbuf;
        float (*ps)[H] = (float(*)[H])(smbuf + 8 * R);

        for (int i = tid; i < 8 * R; i += 256)
            ys[i / R][i % R] = d_rep[mi][r0 + i / R][i % R];
        __syncthreads();

        int h = tid & 127;
        int half = tid >> 7;
        const float* Wc = (mi == 0) ? d_Wxd : d_Wyd;
        float acc[8];
#pragma unroll
        for (int r = 0; r < 8; r++) acc[r] = 0.f;
        int kbeg = half * 128;
#pragma unroll 4
        for (int k = kbeg; k < kbeg + 128; k++) {
            float wv = Wc[k * H + h];
#pragma unroll
            for (int r = 0; r < 8; r++) acc[r] += ys[r][k] * wv;
        }
        if (half == 1) {
#pragma unroll
            for (int r = 0; r < 8; r++) ps[r][h] = acc[r];
        }
        __syncthreads();
        if (half == 0) {
            if (mi == 0) {
                float bb = s_b1[h];
#pragma unroll
                for (int r = 0; r < 8; r++)
                    d_A[(r0 + r) * H + h] = (acc[r] + ps[r][h] + bb) * INV_SQRT2;
            } else {
#pragma unroll
                for (int r = 0; r < 8; r++)
                    d_Bt[mi - 1][h * M + (r0 + r)] = (acc[r] + ps[r][h]) * INV_SQRT2;
            }
        }
    }
}

// ================= K3: score + softmax (hot) =================
__global__ void __launch_bounds__(256) k3_score(
    const float* __restrict__ s_w1, const float* __restrict__ s_w2)
{
    int set = blockIdx.x >> 8;
    int n0 = (blockIdx.x & 255) * 2;
    __shared__ float As[2][H];
    __shared__ float wn_s[H];
    __shared__ float s2h[H];
    __shared__ float logits[2][M];
    __shared__ float nxs[2];
    __shared__ float red[2][8];

    int tid = threadIdx.x;
    As[tid >> 7][tid & 127] = d_A[(n0 + (tid >> 7)) * H + (tid & 127)];
    if (tid < H) {
        wn_s[tid] = s_w1[(3 * R) * H + tid] * INV_SQRT2;
        s2h[tid]  = s_w2[tid] * 0.7071067811865476f;
    }
    if (tid < 2) nxs[tid] = d_norm2[0][n0 + tid];
    __syncthreads();

    int m0 = tid, m1 = tid + 256;
    float ny0 = d_norm2[set + 1][m0];
    float ny1 = d_norm2[set + 1][m1];
    float t00, t01, t10, t11;
    {
        float g00 = d_G[set][(n0 + 0) * M + m0];
        float g01 = d_G[set][(n0 + 0) * M + m1];
        float g10 = d_G[set][(n0 + 1) * M + m0];
        float g11 = d_G[set][(n0 + 1) * M + m1];
        t00 = sqrtf(fmaxf(nxs[0] + ny0 - 2.f * g00, 0.f));
        t01 = sqrtf(fmaxf(nxs[0] + ny1 - 2.f * g01, 0.f));
        t10 = sqrtf(fmaxf(nxs[1] + ny0 - 2.f * g10, 0.f));
        t11 = sqrtf(fmaxf(nxs[1] + ny1 - 2.f * g11, 0.f));
    }

    float acc00 = 0.f, acc01 = 0.f, acc10 = 0.f, acc11 = 0.f;
    const float* Bt = d_Bt[set];
#pragma unroll 4
    for (int k = 0; k < H; k++) {
        float wk = wn_s[k];
        float s2 = s2h[k];
        float bv0 = Bt[k * M + m0];
        float bv1 = Bt[k * M + m1];
        float a0 = As[0][k], a1 = As[1][k];
        float p00 = fmaf(t00, wk, a0 + bv0);
        float p01 = fmaf(t01, wk, a0 + bv1);
        float p10 = fmaf(t10, wk, a1 + bv0);
        float p11 = fmaf(t11, wk, a1 + bv1);
        float e00 = erff(p00), e01 = erff(p01);
        float e10 = erff(p10), e11 = erff(p11);
        float q00 = p00 * s2, q01 = p01 * s2;
        float q10 = p10 * s2, q11 = p11 * s2;
        acc00 = fmaf(q00, e00, acc00 + q00);
        acc01 = fmaf(q01, e01, acc01 + q01);
        acc10 = fmaf(q10, e10, acc10 + q10);
        acc11 = fmaf(q11, e11, acc11 + q11);
    }
    logits[0][m0] = acc00; logits[0][m1] = acc01;
    logits[1][m0] = acc10; logits[1][m1] = acc11;
    __syncthreads();

    int row = tid >> 7;
    int c = tid & 127;
    int w4 = (tid >> 5) & 3;
    int lane = tid & 31;
    float v0 = logits[row][c], v1 = logits[row][c + 128];
    float v2 = logits[row][c + 256], v3 = logits[row][c + 384];
    float mx = fmaxf(fmaxf(v0, v1), fmaxf(v2, v3));
#pragma unroll
    for (int o = 16; o; o >>= 1) mx = fmaxf(mx, __shfl_xor_sync(0xFFFFFFFFu, mx, o));
    if (lane == 0) red[row][w4] = mx;
    __syncthreads();
    mx = fmaxf(fmaxf(red[row][0], red[row][1]), fmaxf(red[row][2], red[row][3]));
    float e0 = __expf(v0 - mx), e1 = __expf(v1 - mx);
    float e2 = __expf(v2 - mx), e3 = __expf(v3 - mx);
    float s = e0 + e1 + e2 + e3;
#pragma unroll
    for (int o = 16; o; o >>= 1) s += __shfl_xor_sync(0xFFFFFFFFu, s, o);
    __syncthreads();
    if (lane == 0) red[row][w4 + 4] = s;
    __syncthreads();
    s = red[row][4] + red[row][5] + red[row][6] + red[row][7];
    float inv = 1.f / s;
    float* Wrow = &d_W[set][(n0 + row) * M];
    Wrow[c] = e0 * inv; Wrow[c + 128] = e1 * inv;
    Wrow[c + 256] = e2 * inv; Wrow[c + 384] = e3 * inv;
}

// ================= K4a: U partials = Wp @ Yp - Wq @ Yn, split-K over M =================
// grid = 64 tiles (16n x 4r) * 4 m-splits = 256 blocks, 256 threads, 2x4 micro
__global__ void __launch_bounds__(256) k4a_u()
{
    __shared__ float w_s[2][16][36];
    __shared__ float yp_s[16][64];
    __shared__ float yn_s[16][64];

    int bid = blockIdx.x;
    int ms = bid & 3;            // m split
    int tile = bid >> 2;         // 0..63
    int bn = (tile >> 2) * 32;   // 16 n-tiles
    int br = (tile & 3) * 64;    // 4 r-tiles
    int tid = threadIdx.x;
    int ty = tid >> 4;
    int tx = tid & 15;

    int wset = tid >> 7;
    int wn = (tid & 127) >> 2;
    int wm = (tid & 3) * 4;
    int ykk = tid >> 4;
    int yc = (tid & 15) * 4;

    float acc[2][4];
#pragma unroll
    for (int i = 0; i < 2; i++)
#pragma unroll
        for (int j = 0; j < 4; j++) acc[i][j] = 0.f;

    int mbase = ms * 128;
    for (int mc = 0; mc < 8; mc++) {
        int mrow = mbase + mc * 16;
        float4 wv  = *(const float4*)&d_W[wset][(bn + wn) * M + mrow + wm];
        float4 ypv = *(const float4*)&d_rep[1][mrow + ykk][br + yc];
        float4 ynv = *(const float4*)&d_rep[2][mrow + ykk][br + yc];
        __syncthreads();
        w_s[wset][wm + 0][wn] = wv.x;
        w_s[wset][wm + 1][wn] = wv.y;
        w_s[wset][wm + 2][wn] = wv.z;
        w_s[wset][wm + 3][wn] = wv.w;
        *(float4*)&yp_s[ykk][yc] = ypv;
        *(float4*)&yn_s[ykk][yc] = ynv;
        __syncthreads();
#pragma unroll
        for (int kk = 0; kk < 16; kk++) {
            float wp0 = w_s[0][kk][ty * 2], wp1 = w_s[0][kk][ty * 2 + 1];
            float wq0 = w_s[1][kk][ty * 2], wq1 = w_s[1][kk][ty * 2 + 1];
            float4 yp = *(const float4*)&yp_s[kk][tx * 4];
            float4 yn = *(const float4*)&yn_s[kk][tx * 4];
            float ypa[4] = {yp.x, yp.y, yp.z, yp.w};
            float yna[4] = {yn.x, yn.y, yn.z, yn.w};
#pragma unroll
            for (int j = 0; j < 4; j++) {
                acc[0][j] += wp0 * ypa[j];
                acc[1][j] += wp1 * ypa[j];
                acc[0][j] -= wq0 * yna[j];
                acc[1][j] -= wq1 * yna[j];
            }
        }
    }
#pragma unroll
    for (int i = 0; i < 2; i++) {
        float4 o = make_float4(acc[i][0], acc[i][1], acc[i][2], acc[i][3]);
        *(float4*)&d_Upart[ms][bn + ty * 2 + i][br + tx * 4] = o;
    }
}

// ================= K4b: out = (sum of U partials) @ out_w =================
// grid = 16 n-tiles(32) x 8 d-tiles(64) = 128 blocks, 256 threads, 2x4 micro
__global__ void __launch_bounds__(256) k4b_out(const float* __restrict__ out_w,
                                               float* __restrict__ out)
{
    __shared__ float us[16][36];   // [k][n], n-tile 32 (+pad)
    __shared__ float ws[16][64];   // [k][d]

    int bid = blockIdx.x;
    int bn = (bid >> 3) * 32;
    int bd = (bid & 7) * 64;
    int tid = threadIdx.x;
    int ty = tid >> 4, tx = tid & 15;

    float acc[2][4];
#pragma unroll
    for (int i = 0; i < 2; i++)
#pragma unroll
        for (int j = 0; j < 4; j++) acc[i][j] = 0.f;

    // load roles
    int un = tid >> 2;            // 0..31  (threads 0..127 handle U)
    int uk = (tid & 3) * 4;
    int t2 = tid - 128;           // threads 128..255 handle W
    int wkk = t2 >> 3;            // 0..15
    int wc = (t2 & 7) * 8;        // 0..56

    for (int kc = 0; kc < R / 16; kc++) {
        float4 uv; float4 wv0, wv1;
        if (tid < 128) {
            const float4* p0 = (const float4*)&d_Upart[0][bn + un][kc * 16 + uk];
            const float4* p1 = (const float4*)&d_Upart[1][bn + un][kc * 16 + uk];
            const float4* p2 = (const float4*)&d_Upart[2][bn + un][kc * 16 + uk];
            const float4* p3 = (const float4*)&d_Upart[3][bn + un][kc * 16 + uk];
            float4 a = *p0, b = *p1, c = *p2, d = *p3;
            uv.x = a.x + b.x + c.x + d.x;
            uv.y = a.y + b.y + c.y + d.y;
            uv.z = a.z + b.z + c.z + d.z;
            uv.w = a.w + b.w + c.w + d.w;
        } else {
            wv0 = *(const float4*)&out_w[(kc * 16 + wkk) * D + bd + wc];
            wv1 = *(const float4*)&out_w[(kc * 16 + wkk) * D + bd + wc + 4];
        }
        __syncthreads();
        if (tid < 128) {
            us[uk + 0][un] = uv.x;
            us[uk + 1][un] = uv.y;
            us[uk + 2][un] = uv.z;
            us[uk + 3][un] = uv.w;
        } else {
            *(float4*)&ws[wkk][wc] = wv0;
            *(float4*)&ws[wkk][wc + 4] = wv1;
        }
        __syncthreads();
#pragma unroll
        for (int kk = 0; kk < 16; kk++) {
            float u0 = us[kk][ty * 2], u1 = us[kk][ty * 2 + 1];
            float4 w4 = *(const float4*)&ws[kk][tx * 4];
            float wa[4] = {w4.x, w4.y, w4.z, w4.w};
#pragma unroll
            for (int j = 0; j < 4; j++) {
                acc[0][j] += u0 * wa[j];
                acc[1][j] += u1 * wa[j];
            }
        }
    }
#pragma unroll
    for (int i = 0; i < 2; i++) {
        float4 o = make_float4(acc[i][0], acc[i][1], acc[i][2], acc[i][3]);
        *(float4*)&out[(bn + ty * 2 + i) * D + bd + tx * 4] = o;
    }
}

// ---------------- launch ----------------
extern "C" void kernel_launch(void* const* d_in, const int* in_sizes, int n_in,
                              void* d_out, int out_size)
{
    const float* feat_x  = (const float*)d_in[0];
    const float* feat_pos= (const float*)d_in[1];
    const float* feat_neg= (const float*)d_in[2];
    const float* g_w1    = (const float*)d_in[3];
    const float* g_b1    = (const float*)d_in[4];
    const float* g_w2    = (const float*)d_in[5];
    const float* g_b2    = (const float*)d_in[6];
    const float* out_w   = (const float*)d_in[7];
    const float* s_w1    = (const float*)d_in[8];
    const float* s_b1    = (const float*)d_in[9];
    const float* s_w2    = (const float*)d_in[10];
    float* out = (float*)d_out;
    (void)in_sizes; (void)n_in; (void)out_size;

    k1_gmlp<<<224, 256>>>(feat_x, feat_pos, feat_neg, g_w1, g_b1, g_w2, g_b2, s_w1);
    k2_gram_ab<<<320, 256>>>(s_b1);
    k3_score<<<512, 256>>>(s_w1, s_w2);
    k4a_u<<<256, 256>>>();
    k4b_out<<<128, 256>>>(out_w, out);
}

// round 5
// speedup vs baseline: 1.7441x; 1.0083x over previous
#include <cuda_runtime.h>
#include <math.h>

#define N 512
#define M 512
#define D 512
#define HG 256
#define R 256
#define H 128

// ---------------- device scratch ----------------
__device__ float d_rep[3][N][R];
__device__ float d_norm2[3][N];
__device__ float d_Wxd[R * H];
__device__ float d_Wyd[R * H];
__device__ float d_A[N * H];        // pre-scaled by 1/sqrt(2)
__device__ float d_Bt[2][H * M];    // pre-scaled by 1/sqrt(2)
__device__ float d_G[2][N * M];
__device__ float d_W[2][N * M];
__device__ float d_Upart[4][N][R];  // split-K partials of U

#define INV_SQRT2 0.7071067811865476f

__device__ __forceinline__ float gelu_exact(float x) {
    return 0.5f * x * (1.0f + erff(x * INV_SQRT2));
}

// Abramowitz-Stegun 7.1.26 erf: |abs err| <= 1.5e-7, branch-free, 2 MUFU.
__device__ __forceinline__ float erf_fast(float x) {
    float ax = fabsf(x);
    float t;
    asm("rcp.approx.f32 %0, %1;" : "=f"(t) : "f"(fmaf(0.3275911f, ax, 1.0f)));
    float p = fmaf(1.061405429f, t, -1.453152027f);
    p = fmaf(p, t, 1.421413741f);
    p = fmaf(p, t, -0.284496736f);
    p = fmaf(p, t, 0.254829592f);
    p = p * t;
    float ex = __expf(-ax * ax);
    float r = fmaf(-p, ex, 1.0f);
    return copysignf(r, x);
}

// ================= K1: g-MLP (+ row norms) and Wxd/Wyd combine =================
__global__ void __launch_bounds__(256) k1_gmlp(
    const float* __restrict__ fx, const float* __restrict__ fp, const float* __restrict__ fn,
    const float* __restrict__ w1, const float* __restrict__ b1,
    const float* __restrict__ w2, const float* __restrict__ b2,
    const float* __restrict__ s_w1)
{
    int bid = blockIdx.x;
    int tid = threadIdx.x;

    if (bid >= 192) {
        int i0 = (bid - 192) * 1024 + tid;
#pragma unroll
        for (int t = 0; t < 4; t++) {
            int i = i0 + t * 256;
            float wd = s_w1[2 * R * H + i];
            d_Wxd[i] = s_w1[i] - wd;
            d_Wyd[i] = s_w1[R * H + i] + wd;
        }
        return;
    }

    int mi = bid / 64;
    int r0 = (bid % 64) * 8;
    const float* X = (mi == 0) ? fx : (mi == 1 ? fp : fn);

    __shared__ float xs[8][D];
    __shared__ float hs[8][HG];
    __shared__ float wsum[8][8];

    for (int i = tid; i < 8 * D; i += 256)
        xs[i / D][i % D] = X[(r0 + i / D) * D + (i % D)];
    __syncthreads();

    int j = tid;
    float acc[8];
#pragma unroll
    for (int r = 0; r < 8; r++) acc[r] = 0.f;
#pragma unroll 4
    for (int k = 0; k < D; k++) {
        float wv = w1[k * HG + j];
#pragma unroll
        for (int r = 0; r < 8; r++) acc[r] += xs[r][k] * wv;
    }
    float bb = b1[j];
#pragma unroll
    for (int r = 0; r < 8; r++) hs[r][j] = gelu_exact(acc[r] + bb);
    __syncthreads();

    float a2[8];
#pragma unroll
    for (int r = 0; r < 8; r++) a2[r] = 0.f;
#pragma unroll 4
    for (int k = 0; k < HG; k++) {
        float wv = w2[k * R + j];
#pragma unroll
        for (int r = 0; r < 8; r++) a2[r] += hs[r][k] * wv;
    }
    float b2v = b2[j];
    int w = tid >> 5, lane = tid & 31;
#pragma unroll
    for (int r = 0; r < 8; r++) {
        float v = a2[r] + b2v;
        d_rep[mi][r0 + r][j] = v;
        float s = v * v;
#pragma unroll
        for (int o = 16; o; o >>= 1) s += __shfl_xor_sync(0xFFFFFFFFu, s, o);
        if (lane == 0) wsum[w][r] = s;
    }
    __syncthreads();
    if (tid < 8) {
        float s = 0.f;
#pragma unroll
        for (int ww = 0; ww < 8; ww++) s += wsum[ww][tid];
        d_norm2[mi][r0 + tid] = s;
    }
}

// ================= K2: Gram (64x64) + A/Bt (split-K, scaled by 1/sqrt2) =================
__global__ void __launch_bounds__(256) k2_gram_ab(const float* __restrict__ s_b1)
{
    __shared__ float smbuf[2 * 32 * 68];
    int bid = blockIdx.x;
    int tid = threadIdx.x;

    if (bid < 128) {
        int set = bid >> 6;
        int tt = bid & 63;
        int bn = (tt >> 3) * 64;
        int bm = (tt & 7) * 64;
        float (*xs)[68]  = (float(*)[68])smbuf;
        float (*ysm)[68] = (float(*)[68])(smbuf + 32 * 68);
        int ty = tid >> 4, tx = tid & 15;

        float acc[4][4];
#pragma unroll
        for (int i = 0; i < 4; i++)
#pragma unroll
            for (int jj = 0; jj < 4; jj++) acc[i][jj] = 0.f;

        for (int kc = 0; kc < R / 32; kc++) {
            __syncthreads();
#pragma unroll
            for (int p = 0; p < 8; p++) {
                int i = tid + p * 256;
                int n = i >> 5, k = i & 31;
                xs[k][n]  = d_rep[0][bn + n][kc * 32 + k];
                ysm[k][n] = d_rep[set + 1][bm + n][kc * 32 + k];
            }
            __syncthreads();
#pragma unroll
            for (int k = 0; k < 32; k++) {
                float4 xv = *(const float4*)&xs[k][ty * 4];
                float4 yv = *(const float4*)&ysm[k][tx * 4];
                float xa[4] = {xv.x, xv.y, xv.z, xv.w};
                float ya[4] = {yv.x, yv.y, yv.z, yv.w};
#pragma unroll
                for (int i = 0; i < 4; i++)
#pragma unroll
                    for (int jj = 0; jj < 4; jj++) acc[i][jj] += xa[i] * ya[jj];
            }
        }
#pragma unroll
        for (int i = 0; i < 4; i++) {
            float4 o = make_float4(acc[i][0], acc[i][1], acc[i][2], acc[i][3]);
            *(float4*)&d_G[set][(bn + ty * 4 + i) * M + bm + tx * 4] = o;
        }
    } else {
        int ab = bid - 128;
        int mi = ab / 64;
        int r0 = (ab % 64) * 8;
        float (*ys)[R] = (float(*)[R])smbuf;
        float (*ps)[H] = (float(*)[H])(smbuf + 8 * R);

        for (int i = tid; i < 8 * R; i += 256)
            ys[i / R][i % R] = d_rep[mi][r0 + i / R][i % R];
        __syncthreads();

        int h = tid & 127;
        int half = tid >> 7;
        const float* Wc = (mi == 0) ? d_Wxd : d_Wyd;
        float acc[8];
#pragma unroll
        for (int r = 0; r < 8; r++) acc[r] = 0.f;
        int kbeg = half * 128;
#pragma unroll 4
        for (int k = kbeg; k < kbeg + 128; k++) {
            float wv = Wc[k * H + h];
#pragma unroll
            for (int r = 0; r < 8; r++) acc[r] += ys[r][k] * wv;
        }
        if (half == 1) {
#pragma unroll
            for (int r = 0; r < 8; r++) ps[r][h] = acc[r];
        }
        __syncthreads();
        if (half == 0) {
            if (mi == 0) {
                float bb = s_b1[h];
#pragma unroll
                for (int r = 0; r < 8; r++)
                    d_A[(r0 + r) * H + h] = (acc[r] + ps[r][h] + bb) * INV_SQRT2;
            } else {
#pragma unroll
                for (int r = 0; r < 8; r++)
                    d_Bt[mi - 1][h * M + (r0 + r)] = (acc[r] + ps[r][h]) * INV_SQRT2;
            }
        }
    }
}

// ================= K3: score + softmax (hot) =================
__global__ void __launch_bounds__(256) k3_score(
    const float* __restrict__ s_w1, const float* __restrict__ s_w2)
{
    int set = blockIdx.x >> 8;
    int n0 = (blockIdx.x & 255) * 2;
    __shared__ float As[2][H];
    __shared__ float wn_s[H];
    __shared__ float s2h[H];
    __shared__ float logits[2][M];
    __shared__ float nxs[2];
    __shared__ float red[2][8];

    int tid = threadIdx.x;
    As[tid >> 7][tid & 127] = d_A[(n0 + (tid >> 7)) * H + (tid & 127)];
    if (tid < H) {
        wn_s[tid] = s_w1[(3 * R) * H + tid] * INV_SQRT2;
        s2h[tid]  = s_w2[tid] * 0.7071067811865476f;
    }
    if (tid < 2) nxs[tid] = d_norm2[0][n0 + tid];
    __syncthreads();

    int m0 = tid, m1 = tid + 256;
    float ny0 = d_norm2[set + 1][m0];
    float ny1 = d_norm2[set + 1][m1];
    float t00, t01, t10, t11;
    {
        float g00 = d_G[set][(n0 + 0) * M + m0];
        float g01 = d_G[set][(n0 + 0) * M + m1];
        float g10 = d_G[set][(n0 + 1) * M + m0];
        float g11 = d_G[set][(n0 + 1) * M + m1];
        t00 = sqrtf(fmaxf(nxs[0] + ny0 - 2.f * g00, 0.f));
        t01 = sqrtf(fmaxf(nxs[0] + ny1 - 2.f * g01, 0.f));
        t10 = sqrtf(fmaxf(nxs[1] + ny0 - 2.f * g10, 0.f));
        t11 = sqrtf(fmaxf(nxs[1] + ny1 - 2.f * g11, 0.f));
    }

    float acc00 = 0.f, acc01 = 0.f, acc10 = 0.f, acc11 = 0.f;
    const float* Bt = d_Bt[set];
#pragma unroll 4
    for (int k = 0; k < H; k++) {
        float wk = wn_s[k];
        float s2 = s2h[k];
        float bv0 = Bt[k * M + m0];
        float bv1 = Bt[k * M + m1];
        float a0 = As[0][k], a1 = As[1][k];
        float p00 = fmaf(t00, wk, a0 + bv0);
        float p01 = fmaf(t01, wk, a0 + bv1);
        float p10 = fmaf(t10, wk, a1 + bv0);
        float p11 = fmaf(t11, wk, a1 + bv1);
        float e00 = erf_fast(p00), e01 = erf_fast(p01);
        float e10 = erf_fast(p10), e11 = erf_fast(p11);
        float q00 = p00 * s2, q01 = p01 * s2;
        float q10 = p10 * s2, q11 = p11 * s2;
        acc00 = fmaf(q00, e00, acc00 + q00);
        acc01 = fmaf(q01, e01, acc01 + q01);
        acc10 = fmaf(q10, e10, acc10 + q10);
        acc11 = fmaf(q11, e11, acc11 + q11);
    }
    logits[0][m0] = acc00; logits[0][m1] = acc01;
    logits[1][m0] = acc10; logits[1][m1] = acc11;
    __syncthreads();

    int row = tid >> 7;
    int c = tid & 127;
    int w4 = (tid >> 5) & 3;
    int lane = tid & 31;
    float v0 = logits[row][c], v1 = logits[row][c + 128];
    float v2 = logits[row][c + 256], v3 = logits[row][c + 384];
    float mx = fmaxf(fmaxf(v0, v1), fmaxf(v2, v3));
#pragma unroll
    for (int o = 16; o; o >>= 1) mx = fmaxf(mx, __shfl_xor_sync(0xFFFFFFFFu, mx, o));
    if (lane == 0) red[row][w4] = mx;
    __syncthreads();
    mx = fmaxf(fmaxf(red[row][0], red[row][1]), fmaxf(red[row][2], red[row][3]));
    float e0 = __expf(v0 - mx), e1 = __expf(v1 - mx);
    float e2 = __expf(v2 - mx), e3 = __expf(v3 - mx);
    float s = e0 + e1 + e2 + e3;
#pragma unroll
    for (int o = 16; o; o >>= 1) s += __shfl_xor_sync(0xFFFFFFFFu, s, o);
    __syncthreads();
    if (lane == 0) red[row][w4 + 4] = s;
    __syncthreads();
    s = red[row][4] + red[row][5] + red[row][6] + red[row][7];
    float inv = 1.f / s;
    float* Wrow = &d_W[set][(n0 + row) * M];
    Wrow[c] = e0 * inv; Wrow[c + 128] = e1 * inv;
    Wrow[c + 256] = e2 * inv; Wrow[c + 384] = e3 * inv;
}

// ================= K4a: U partials = Wp @ Yp - Wq @ Yn, split-K over M =================
__global__ void __launch_bounds__(256) k4a_u()
{
    __shared__ float w_s[2][16][36];
    __shared__ float yp_s[16][64];
    __shared__ float yn_s[16][64];

    int bid = blockIdx.x;
    int ms = bid & 3;
    int tile = bid >> 2;
    int bn = (tile >> 2) * 32;
    int br = (tile & 3) * 64;
    int tid = threadIdx.x;
    int ty = tid >> 4;
    int tx = tid & 15;

    int wset = tid >> 7;
    int wn = (tid & 127) >> 2;
    int wm = (tid & 3) * 4;
    int ykk = tid >> 4;
    int yc = (tid & 15) * 4;

    float acc[2][4];
#pragma unroll
    for (int i = 0; i < 2; i++)
#pragma unroll
        for (int j = 0; j < 4; j++) acc[i][j] = 0.f;

    int mbase = ms * 128;
    for (int mc = 0; mc < 8; mc++) {
        int mrow = mbase + mc * 16;
        float4 wv  = *(const float4*)&d_W[wset][(bn + wn) * M + mrow + wm];
        float4 ypv = *(const float4*)&d_rep[1][mrow + ykk][br + yc];
        float4 ynv = *(const float4*)&d_rep[2][mrow + ykk][br + yc];
        __syncthreads();
        w_s[wset][wm + 0][wn] = wv.x;
        w_s[wset][wm + 1][wn] = wv.y;
        w_s[wset][wm + 2][wn] = wv.z;
        w_s[wset][wm + 3][wn] = wv.w;
        *(float4*)&yp_s[ykk][yc] = ypv;
        *(float4*)&yn_s[ykk][yc] = ynv;
        __syncthreads();
#pragma unroll
        for (int kk = 0; kk < 16; kk++) {
            float wp0 = w_s[0][kk][ty * 2], wp1 = w_s[0][kk][ty * 2 + 1];
            float wq0 = w_s[1][kk][ty * 2], wq1 = w_s[1][kk][ty * 2 + 1];
            float4 yp = *(const float4*)&yp_s[kk][tx * 4];
            float4 yn = *(const float4*)&yn_s[kk][tx * 4];
            float ypa[4] = {yp.x, yp.y, yp.z, yp.w};
            float yna[4] = {yn.x, yn.y, yn.z, yn.w};
#pragma unroll
            for (int j = 0; j < 4; j++) {
                acc[0][j] += wp0 * ypa[j];
                acc[1][j] += wp1 * ypa[j];
                acc[0][j] -= wq0 * yna[j];
                acc[1][j] -= wq1 * yna[j];
            }
        }
    }
#pragma unroll
    for (int i = 0; i < 2; i++) {
        float4 o = make_float4(acc[i][0], acc[i][1], acc[i][2], acc[i][3]);
        *(float4*)&d_Upart[ms][bn + ty * 2 + i][br + tx * 4] = o;
    }
}

// ================= K4b: out = (sum of U partials) @ out_w =================
__global__ void __launch_bounds__(256) k4b_out(const float* __restrict__ out_w,
                                               float* __restrict__ out)
{
    __shared__ float us[16][36];
    __shared__ float ws[16][64];

    int bid = blockIdx.x;
    int bn = (bid >> 3) * 32;
    int bd = (bid & 7) * 64;
    int tid = threadIdx.x;
    int ty = tid >> 4, tx = tid & 15;

    float acc[2][4];
#pragma unroll
    for (int i = 0; i < 2; i++)
#pragma unroll
        for (int j = 0; j < 4; j++) acc[i][j] = 0.f;

    int un = tid >> 2;
    int uk = (tid & 3) * 4;
    int t2 = tid - 128;
    int wkk = t2 >> 3;
    int wc = (t2 & 7) * 8;

    for (int kc = 0; kc < R / 16; kc++) {
        float4 uv; float4 wv0, wv1;
        if (tid < 128) {
            float4 a = *(const float4*)&d_Upart[0][bn + un][kc * 16 + uk];
            float4 b = *(const float4*)&d_Upart[1][bn + un][kc * 16 + uk];
            float4 c = *(const float4*)&d_Upart[2][bn + un][kc * 16 + uk];
            float4 d = *(const float4*)&d_Upart[3][bn + un][kc * 16 + uk];
            uv.x = a.x + b.x + c.x + d.x;
            uv.y = a.y + b.y + c.y + d.y;
            uv.z = a.z + b.z + c.z + d.z;
            uv.w = a.w + b.w + c.w + d.w;
        } else {
            wv0 = *(const float4*)&out_w[(kc * 16 + wkk) * D + bd + wc];
            wv1 = *(const float4*)&out_w[(kc * 16 + wkk) * D + bd + wc + 4];
        }
        __syncthreads();
        if (tid < 128) {
            us[uk + 0][un] = uv.x;
            us[uk + 1][un] = uv.y;
            us[uk + 2][un] = uv.z;
            us[uk + 3][un] = uv.w;
        } else {
            *(float4*)&ws[wkk][wc] = wv0;
            *(float4*)&ws[wkk][wc + 4] = wv1;
        }
        __syncthreads();
#pragma unroll
        for (int kk = 0; kk < 16; kk++) {
            float u0 = us[kk][ty * 2], u1 = us[kk][ty * 2 + 1];
            float4 w4 = *(const float4*)&ws[kk][tx * 4];
            float wa[4] = {w4.x, w4.y, w4.z, w4.w};
#pragma unroll
            for (int j = 0; j < 4; j++) {
                acc[0][j] += u0 * wa[j];
                acc[1][j] += u1 * wa[j];
            }
        }
    }
#pragma unroll
    for (int i = 0; i < 2; i++) {
        float4 o = make_float4(acc[i][0], acc[i][1], acc[i][2], acc[i][3]);
        *(float4*)&out[(bn + ty * 2 + i) * D + bd + tx * 4] = o;
    }
}

// ---------------- launch ----------------
extern "C" void kernel_launch(void* const* d_in, const int* in_sizes, int n_in,
                              void* d_out, int out_size)
{
    const float* feat_x  = (const float*)d_in[0];
    const float* feat_pos= (const float*)d_in[1];
    const float* feat_neg= (const float*)d_in[2];
    const float* g_w1    = (const float*)d_in[3];
    const float* g_b1    = (const float*)d_in[4];
    const float* g_w2    = (const float*)d_in[5];
    const float* g_b2    = (const float*)d_in[6];
    const float* out_w   = (const float*)d_in[7];
    const float* s_w1    = (const float*)d_in[8];
    const float* s_b1    = (const float*)d_in[9];
    const float* s_w2    = (const float*)d_in[10];
    float* out = (float*)d_out;
    (void)in_sizes; (void)n_in; (void)out_size;

    k1_gmlp<<<224, 256>>>(feat_x, feat_pos, feat_neg, g_w1, g_b1, g_w2, g_b2, s_w1);
    k2_gram_ab<<<320, 256>>>(s_b1);
    k3_score<<<512, 256>>>(s_w1, s_w2);
    k4a_u<<<256, 256>>>();
    k4b_out<<<128, 256>>>(out_w, out);
}